// round 1
// baseline (speedup 1.0000x reference)
#include <cuda_runtime.h>
#include <math.h>

#define TOKS 8192
#define DM   1024
#define NE   8
#define DFF  4096
#define NASSIGN (TOKS * 2)
#define GATE_BLOCKS (TOKS / 8)

// ------------- scratch (static device memory; no allocations) -------------
__device__ float g_h[(size_t)NASSIGN * DFF];   // 256 MB: gelu(x@W1) per assignment
__device__ float g_y[(size_t)NASSIGN * DM];    //  64 MB: w*(h@W2) per assignment
__device__ int   g_rowlist[NASSIGN];           // slot -> token
__device__ float g_wlist[NASSIGN];             // slot -> combine weight
__device__ int   g_slot_of[NASSIGN];           // (t,k) -> slot
__device__ int   g_topi[NASSIGN];
__device__ float g_topw[NASSIGN];
__device__ int   g_count[NE];
__device__ int   g_fill[NE];
__device__ int   g_off[NE];
__device__ float g_blockprob[GATE_BLOCKS * NE];

// ---------------------------------------------------------------------------
__global__ void zero_counters() {
    int i = threadIdx.x;
    if (i < NE) { g_count[i] = 0; g_fill[i] = 0; }
}

// One warp per token; 8 warps (8 tokens) per block.
__global__ __launch_bounds__(256) void gate_kernel(
    const float* __restrict__ x, const float* __restrict__ Wg)
{
    int warp = threadIdx.x >> 5, lane = threadIdx.x & 31;
    int t = blockIdx.x * 8 + warp;
    __shared__ float probs_sh[8][NE];

    float acc[NE];
#pragma unroll
    for (int e = 0; e < NE; e++) acc[e] = 0.f;
    const float* xr = x + (size_t)t * DM;
    for (int i = lane; i < DM; i += 32) {
        float xv = xr[i];
#pragma unroll
        for (int e = 0; e < NE; e++) acc[e] += xv * Wg[i * NE + e];
    }
#pragma unroll
    for (int off = 16; off; off >>= 1)
#pragma unroll
        for (int e = 0; e < NE; e++)
            acc[e] += __shfl_xor_sync(0xFFFFFFFFu, acc[e], off);

    if (lane == 0) {
        float mx = acc[0];
#pragma unroll
        for (int e = 1; e < NE; e++) mx = fmaxf(mx, acc[e]);
        float p[NE], s = 0.f;
#pragma unroll
        for (int e = 0; e < NE; e++) { p[e] = __expf(acc[e] - mx); s += p[e]; }
        float inv = 1.f / s;
#pragma unroll
        for (int e = 0; e < NE; e++) p[e] *= inv;
        // top-2, stable (first index wins ties) matching jax top_k
        int i0 = 0;
#pragma unroll
        for (int e = 1; e < NE; e++) if (p[e] > p[i0]) i0 = e;
        int i1 = (i0 == 0) ? 1 : 0;
#pragma unroll
        for (int e = 0; e < NE; e++) if (e != i0 && p[e] > p[i1]) i1 = e;
        float v0 = p[i0], v1 = p[i1];
        float s2 = 1.f / (v0 + v1 + 1e-8f);
        g_topi[t * 2 + 0] = i0;  g_topw[t * 2 + 0] = v0 * s2;
        g_topi[t * 2 + 1] = i1;  g_topw[t * 2 + 1] = v1 * s2;
        atomicAdd(&g_count[i0], 1);
        atomicAdd(&g_count[i1], 1);
#pragma unroll
        for (int e = 0; e < NE; e++) probs_sh[warp][e] = p[e];
    }
    __syncthreads();
    if (threadIdx.x < NE) {
        float s = 0.f;
#pragma unroll
        for (int w = 0; w < 8; w++) s += probs_sh[w][threadIdx.x];
        g_blockprob[blockIdx.x * NE + threadIdx.x] = s;
    }
}

__global__ void offsets_kernel() {
    if (threadIdx.x == 0) {
        int o = 0;
        for (int e = 0; e < NE; e++) { g_off[e] = o; o += g_count[e]; }
    }
}

__global__ void build_kernel() {
    int a = blockIdx.x * blockDim.x + threadIdx.x;
    if (a >= NASSIGN) return;
    int e = g_topi[a];
    int pos = atomicAdd(&g_fill[e], 1);
    int slot = g_off[e] + pos;
    g_rowlist[slot] = a >> 1;
    g_wlist[slot] = g_topw[a];
    g_slot_of[a] = slot;
}

// ----------------- grouped GEMM 1: h = gelu(x_gather @ W1[e]) --------------
// 128x128x16 tile, 256 threads, 8x8 microkernel.
__global__ __launch_bounds__(256) void gemm1_kernel(
    const float* __restrict__ x, const float* __restrict__ W1)
{
    int e = blockIdx.z;
    int M = g_count[e];
    int m0 = blockIdx.y * 128;
    if (m0 >= M) return;
    int n0 = blockIdx.x * 128;
    int base = g_off[e];
    const float* W = W1 + (size_t)e * DM * DFF;

    __shared__ float As[16][132];
    __shared__ float Bs[16][128];

    int tid = threadIdx.x;
    int ty = tid >> 4, tx = tid & 15;
    float acc[8][8];
#pragma unroll
    for (int i = 0; i < 8; i++)
#pragma unroll
        for (int j = 0; j < 8; j++) acc[i][j] = 0.f;

    // precompute gathered row pointers valid for all k-steps
    for (int k0 = 0; k0 < DM; k0 += 16) {
#pragma unroll
        for (int it = 0; it < 2; it++) {
            int f = tid + it * 256;             // 0..511 float4s of A tile
            int row = f >> 2, kq = (f & 3) * 4;
            float4 v = make_float4(0.f, 0.f, 0.f, 0.f);
            if (m0 + row < M) {
                int tok = g_rowlist[base + m0 + row];
                v = *(const float4*)(x + (size_t)tok * DM + k0 + kq);
            }
            As[kq + 0][row] = v.x; As[kq + 1][row] = v.y;
            As[kq + 2][row] = v.z; As[kq + 3][row] = v.w;
        }
#pragma unroll
        for (int it = 0; it < 2; it++) {
            int f = tid + it * 256;             // 0..511 float4s of B tile
            int kr = f >> 5, c4 = (f & 31) * 4;
            *(float4*)&Bs[kr][c4] =
                *(const float4*)(W + (size_t)(k0 + kr) * DFF + n0 + c4);
        }
        __syncthreads();
#pragma unroll
        for (int kk = 0; kk < 16; kk++) {
            float a[8], b[8];
            *(float4*)(a)     = *(float4*)&As[kk][ty * 8];
            *(float4*)(a + 4) = *(float4*)&As[kk][ty * 8 + 4];
            *(float4*)(b)     = *(float4*)&Bs[kk][tx * 8];
            *(float4*)(b + 4) = *(float4*)&Bs[kk][tx * 8 + 4];
#pragma unroll
            for (int i = 0; i < 8; i++)
#pragma unroll
                for (int j = 0; j < 8; j++) acc[i][j] = fmaf(a[i], b[j], acc[i][j]);
        }
        __syncthreads();
    }
#pragma unroll
    for (int i = 0; i < 8; i++) {
        int row = m0 + ty * 8 + i;
        if (row >= M) break;
        float* dst = g_h + (size_t)(base + row) * DFF + n0 + tx * 8;
#pragma unroll
        for (int j = 0; j < 8; j++) {
            float v = acc[i][j];
            dst[j] = 0.5f * v * (1.0f + erff(v * 0.70710678118654752f));
        }
    }
}

// ----------------- grouped GEMM 2: y = w * (h @ W2[e]) ---------------------
__global__ __launch_bounds__(256) void gemm2_kernel(
    const float* __restrict__ W2)
{
    int e = blockIdx.z;
    int M = g_count[e];
    int m0 = blockIdx.y * 128;
    if (m0 >= M) return;
    int n0 = blockIdx.x * 128;
    int base = g_off[e];
    const float* W = W2 + (size_t)e * DFF * DM;

    __shared__ float As[16][132];
    __shared__ float Bs[16][128];

    int tid = threadIdx.x;
    int ty = tid >> 4, tx = tid & 15;
    float acc[8][8];
#pragma unroll
    for (int i = 0; i < 8; i++)
#pragma unroll
        for (int j = 0; j < 8; j++) acc[i][j] = 0.f;

    for (int k0 = 0; k0 < DFF; k0 += 16) {
#pragma unroll
        for (int it = 0; it < 2; it++) {
            int f = tid + it * 256;
            int row = f >> 2, kq = (f & 3) * 4;
            float4 v = make_float4(0.f, 0.f, 0.f, 0.f);
            if (m0 + row < M)
                v = *(const float4*)(g_h + (size_t)(base + m0 + row) * DFF + k0 + kq);
            As[kq + 0][row] = v.x; As[kq + 1][row] = v.y;
            As[kq + 2][row] = v.z; As[kq + 3][row] = v.w;
        }
#pragma unroll
        for (int it = 0; it < 2; it++) {
            int f = tid + it * 256;
            int kr = f >> 5, c4 = (f & 31) * 4;
            *(float4*)&Bs[kr][c4] =
                *(const float4*)(W + (size_t)(k0 + kr) * DM + n0 + c4);
        }
        __syncthreads();
#pragma unroll
        for (int kk = 0; kk < 16; kk++) {
            float a[8], b[8];
            *(float4*)(a)     = *(float4*)&As[kk][ty * 8];
            *(float4*)(a + 4) = *(float4*)&As[kk][ty * 8 + 4];
            *(float4*)(b)     = *(float4*)&Bs[kk][tx * 8];
            *(float4*)(b + 4) = *(float4*)&Bs[kk][tx * 8 + 4];
#pragma unroll
            for (int i = 0; i < 8; i++)
#pragma unroll
                for (int j = 0; j < 8; j++) acc[i][j] = fmaf(a[i], b[j], acc[i][j]);
        }
        __syncthreads();
    }
#pragma unroll
    for (int i = 0; i < 8; i++) {
        int row = m0 + ty * 8 + i;
        if (row >= M) break;
        int slot = base + row;
        float w = g_wlist[slot];
        float* dst = g_y + (size_t)slot * DM + n0 + tx * 8;
#pragma unroll
        for (int j = 0; j < 8; j++) dst[j] = w * acc[i][j];
    }
}

// ----------------- combine: out[t] = y[slot0] + y[slot1] -------------------
__global__ void combine_kernel(float* __restrict__ out) {
    int idx = blockIdx.x * blockDim.x + threadIdx.x;   // over TOKS*DM/4
    if (idx >= TOKS * DM / 4) return;
    int t  = idx / (DM / 4);
    int d4 = idx % (DM / 4);
    int s0 = g_slot_of[t * 2 + 0];
    int s1 = g_slot_of[t * 2 + 1];
    float4 a = *(const float4*)(g_y + (size_t)s0 * DM + d4 * 4);
    float4 b = *(const float4*)(g_y + (size_t)s1 * DM + d4 * 4);
    float4 r = make_float4(a.x + b.x, a.y + b.y, a.z + b.z, a.w + b.w);
    ((float4*)out)[idx] = r;
}

// ----------------- load-balance loss ---------------------------------------
__global__ void loss_kernel(float* __restrict__ out, int out_size) {
    __shared__ float sh[256];
    int e = threadIdx.x & 7, part = threadIdx.x >> 3;   // 32 parts x 8 experts
    float s = 0.f;
    for (int b = part; b < GATE_BLOCKS; b += 32) s += g_blockprob[b * NE + e];
    sh[threadIdx.x] = s;
    __syncthreads();
    if (threadIdx.x < NE) {
        float rp = 0.f;
        for (int p = 0; p < 32; p++) rp += sh[p * NE + threadIdx.x];
        rp /= (float)TOKS;                               // router_probs[e]
        float usage = (float)g_count[threadIdx.x] / (float)NASSIGN;
        sh[threadIdx.x] = rp * usage;
    }
    __syncthreads();
    if (threadIdx.x == 0) {
        float loss = 0.f;
        for (int e2 = 0; e2 < NE; e2++) loss += sh[e2];
        loss *= (float)NE;
        if (out_size > TOKS * DM) out[TOKS * DM] = loss;
    }
}

// ---------------------------------------------------------------------------
extern "C" void kernel_launch(void* const* d_in, const int* in_sizes, int n_in,
                              void* d_out, int out_size)
{
    const float* x  = (const float*)d_in[0];
    const float* Wg = (const float*)d_in[1];
    const float* W1 = (const float*)d_in[2];
    const float* W2 = (const float*)d_in[3];
    float* out = (float*)d_out;

    zero_counters<<<1, 32>>>();
    gate_kernel<<<GATE_BLOCKS, 256>>>(x, Wg);
    offsets_kernel<<<1, 32>>>();
    build_kernel<<<(NASSIGN + 255) / 256, 256>>>();

    gemm1_kernel<<<dim3(DFF / 128, TOKS * 2 / 128, NE), 256>>>(x, W1);
    gemm2_kernel<<<dim3(DM / 128, TOKS * 2 / 128, NE), 256>>>(W2);

    combine_kernel<<<(TOKS * DM / 4 + 255) / 256, 256>>>(out);
    loss_kernel<<<1, 256>>>(out, out_size);
}

// round 2
// speedup vs baseline: 2.8612x; 2.8612x over previous
#include <cuda_runtime.h>
#include <math.h>
#include <stdint.h>

#define TOKS 8192
#define DM   1024
#define NE   8
#define DFF  4096
#define NASSIGN (TOKS * 2)
#define GATE_BLOCKS (TOKS / 8)

// ------------- scratch (static device memory; no allocations) -------------
__device__ float g_h[(size_t)NASSIGN * DFF];   // 256 MB: gelu(x@W1) per assignment
__device__ float g_y[(size_t)NASSIGN * DM];    //  64 MB: w*(h@W2) per assignment
__device__ int   g_rowlist[NASSIGN];           // slot -> token
__device__ float g_wlist[NASSIGN];             // slot -> combine weight
__device__ int   g_slot_of[NASSIGN];           // (t,k) -> slot
__device__ int   g_topi[NASSIGN];
__device__ float g_topw[NASSIGN];
__device__ int   g_count[NE];
__device__ int   g_fill[NE];
__device__ int   g_off[NE];
__device__ float g_blockprob[GATE_BLOCKS * NE];

// ---------------------------------------------------------------------------
__global__ void zero_counters() {
    int i = threadIdx.x;
    if (i < NE) { g_count[i] = 0; g_fill[i] = 0; }
}

// One warp per token; 8 warps (8 tokens) per block.
__global__ __launch_bounds__(256) void gate_kernel(
    const float* __restrict__ x, const float* __restrict__ Wg)
{
    int warp = threadIdx.x >> 5, lane = threadIdx.x & 31;
    int t = blockIdx.x * 8 + warp;
    __shared__ float probs_sh[8][NE];

    float acc[NE];
#pragma unroll
    for (int e = 0; e < NE; e++) acc[e] = 0.f;
    const float* xr = x + (size_t)t * DM;
    for (int i = lane; i < DM; i += 32) {
        float xv = xr[i];
#pragma unroll
        for (int e = 0; e < NE; e++) acc[e] += xv * Wg[i * NE + e];
    }
#pragma unroll
    for (int off = 16; off; off >>= 1)
#pragma unroll
        for (int e = 0; e < NE; e++)
            acc[e] += __shfl_xor_sync(0xFFFFFFFFu, acc[e], off);

    if (lane == 0) {
        float mx = acc[0];
#pragma unroll
        for (int e = 1; e < NE; e++) mx = fmaxf(mx, acc[e]);
        float p[NE], s = 0.f;
#pragma unroll
        for (int e = 0; e < NE; e++) { p[e] = __expf(acc[e] - mx); s += p[e]; }
        float inv = 1.f / s;
#pragma unroll
        for (int e = 0; e < NE; e++) p[e] *= inv;
        int i0 = 0;
#pragma unroll
        for (int e = 1; e < NE; e++) if (p[e] > p[i0]) i0 = e;
        int i1 = (i0 == 0) ? 1 : 0;
#pragma unroll
        for (int e = 0; e < NE; e++) if (e != i0 && p[e] > p[i1]) i1 = e;
        float v0 = p[i0], v1 = p[i1];
        float s2 = 1.f / (v0 + v1 + 1e-8f);
        g_topi[t * 2 + 0] = i0;  g_topw[t * 2 + 0] = v0 * s2;
        g_topi[t * 2 + 1] = i1;  g_topw[t * 2 + 1] = v1 * s2;
        atomicAdd(&g_count[i0], 1);
        atomicAdd(&g_count[i1], 1);
#pragma unroll
        for (int e = 0; e < NE; e++) probs_sh[warp][e] = p[e];
    }
    __syncthreads();
    if (threadIdx.x < NE) {
        float s = 0.f;
#pragma unroll
        for (int w = 0; w < 8; w++) s += probs_sh[w][threadIdx.x];
        g_blockprob[blockIdx.x * NE + threadIdx.x] = s;
    }
}

__global__ void offsets_kernel() {
    if (threadIdx.x == 0) {
        int o = 0;
        for (int e = 0; e < NE; e++) { g_off[e] = o; o += g_count[e]; }
    }
}

__global__ void build_kernel() {
    int a = blockIdx.x * blockDim.x + threadIdx.x;
    if (a >= NASSIGN) return;
    int e = g_topi[a];
    int pos = atomicAdd(&g_fill[e], 1);
    int slot = g_off[e] + pos;
    g_rowlist[slot] = a >> 1;
    g_wlist[slot] = g_topw[a];
    g_slot_of[a] = slot;
}

// ======================= tf32 tensor-core GEMMs ============================
// 128x128x32 block tile, 256 threads = 8 warps, warp tile 32x64 via
// mma.sync.m16n8k8.tf32 (2 m-frags x 8 n-frags, fp32 accumulate).

__device__ __forceinline__ float f2tf32(float v) {
    uint32_t u;
    asm("cvt.rna.tf32.f32 %0, %1;" : "=r"(u) : "f"(v));
    return __uint_as_float(u);
}

__device__ __forceinline__ void mma_tf32(float* c, const uint32_t* a, const uint32_t* b) {
    asm volatile(
        "mma.sync.aligned.m16n8k8.row.col.f32.tf32.tf32.f32 "
        "{%0,%1,%2,%3}, {%4,%5,%6,%7}, {%8,%9}, {%0,%1,%2,%3};"
        : "+f"(c[0]), "+f"(c[1]), "+f"(c[2]), "+f"(c[3])
        : "r"(a[0]), "r"(a[1]), "r"(a[2]), "r"(a[3]), "r"(b[0]), "r"(b[1]));
}

#define BM 128
#define BN 128
#define BK 32
#define A_PAD 4     // As row stride 36 words -> conflict-free frag LDS + STS.128
#define B_PAD 8     // Bs row stride 136 words -> conflict-free frag LDS + STS.128

// GEMM1: h = gelu(x_gather @ W1[e]),  K = DM, N = DFF
__global__ __launch_bounds__(256, 2) void gemm1_tc(
    const float* __restrict__ x, const float* __restrict__ W1)
{
    int e = blockIdx.z;
    int M = g_count[e];
    int m0 = blockIdx.y * BM;
    if (m0 >= M) return;
    int n0 = blockIdx.x * BN;
    int base = g_off[e];
    const float* W = W1 + (size_t)e * DM * DFF;   // [K][N]

    __shared__ float As[BM][BK + A_PAD];
    __shared__ float Bs[BK][BN + B_PAD];

    int tid = threadIdx.x;
    int lane = tid & 31, warp = tid >> 5;
    int wm = (warp & 3) * 32;
    int wn = (warp >> 2) * 64;
    int g = lane >> 2, tig = lane & 3;

    // 4 gathered A-row pointers per thread (clamped; garbage rows unused)
    const float* arow[4];
    int kq = (tid & 7) * 4;
#pragma unroll
    for (int it = 0; it < 4; it++) {
        int row = (tid >> 3) + it * 32;
        int r = m0 + row; if (r >= M) r = M - 1;
        arow[it] = x + (size_t)g_rowlist[base + r] * DM;
    }

    float acc[2][8][4];
#pragma unroll
    for (int i = 0; i < 2; i++)
#pragma unroll
        for (int j = 0; j < 8; j++)
#pragma unroll
            for (int c = 0; c < 4; c++) acc[i][j][c] = 0.f;

    for (int k0 = 0; k0 < DM; k0 += BK) {
#pragma unroll
        for (int it = 0; it < 4; it++) {
            int row = (tid >> 3) + it * 32;
            float4 v = *(const float4*)(arow[it] + k0 + kq);
            float4 t = make_float4(f2tf32(v.x), f2tf32(v.y), f2tf32(v.z), f2tf32(v.w));
            *(float4*)&As[row][kq] = t;
        }
#pragma unroll
        for (int it = 0; it < 4; it++) {
            int f = tid + it * 256;
            int kr = f >> 5, c4 = (f & 31) * 4;
            float4 v = *(const float4*)(W + (size_t)(k0 + kr) * DFF + n0 + c4);
            float4 t = make_float4(f2tf32(v.x), f2tf32(v.y), f2tf32(v.z), f2tf32(v.w));
            *(float4*)&Bs[kr][c4] = t;
        }
        __syncthreads();
#pragma unroll
        for (int ks = 0; ks < BK; ks += 8) {
            uint32_t af[2][4];
#pragma unroll
            for (int i = 0; i < 2; i++) {
                af[i][0] = __float_as_uint(As[wm + i * 16 + g][ks + tig]);
                af[i][1] = __float_as_uint(As[wm + i * 16 + g + 8][ks + tig]);
                af[i][2] = __float_as_uint(As[wm + i * 16 + g][ks + tig + 4]);
                af[i][3] = __float_as_uint(As[wm + i * 16 + g + 8][ks + tig + 4]);
            }
            uint32_t bf[8][2];
#pragma unroll
            for (int j = 0; j < 8; j++) {
                bf[j][0] = __float_as_uint(Bs[ks + tig][wn + j * 8 + g]);
                bf[j][1] = __float_as_uint(Bs[ks + tig + 4][wn + j * 8 + g]);
            }
#pragma unroll
            for (int i = 0; i < 2; i++)
#pragma unroll
                for (int j = 0; j < 8; j++) mma_tf32(acc[i][j], af[i], bf[j]);
        }
        __syncthreads();
    }
    // epilogue: gelu -> g_h
#pragma unroll
    for (int i = 0; i < 2; i++) {
        int r0 = m0 + wm + i * 16 + g;
        int r1 = r0 + 8;
#pragma unroll
        for (int j = 0; j < 8; j++) {
            int col = n0 + wn + j * 8 + 2 * tig;
            if (r0 < M) {
                float* d = g_h + (size_t)(base + r0) * DFF + col;
                float v0 = acc[i][j][0], v1 = acc[i][j][1];
                d[0] = 0.5f * v0 * (1.0f + erff(v0 * 0.70710678118654752f));
                d[1] = 0.5f * v1 * (1.0f + erff(v1 * 0.70710678118654752f));
            }
            if (r1 < M) {
                float* d = g_h + (size_t)(base + r1) * DFF + col;
                float v2 = acc[i][j][2], v3 = acc[i][j][3];
                d[0] = 0.5f * v2 * (1.0f + erff(v2 * 0.70710678118654752f));
                d[1] = 0.5f * v3 * (1.0f + erff(v3 * 0.70710678118654752f));
            }
        }
    }
}

// GEMM2: y = w * (h @ W2[e]),  K = DFF, N = DM
__global__ __launch_bounds__(256, 2) void gemm2_tc(
    const float* __restrict__ W2)
{
    int e = blockIdx.z;
    int M = g_count[e];
    int m0 = blockIdx.y * BM;
    if (m0 >= M) return;
    int n0 = blockIdx.x * BN;
    int base = g_off[e];
    const float* W = W2 + (size_t)e * DFF * DM;   // [K][N]

    __shared__ float As[BM][BK + A_PAD];
    __shared__ float Bs[BK][BN + B_PAD];

    int tid = threadIdx.x;
    int lane = tid & 31, warp = tid >> 5;
    int wm = (warp & 3) * 32;
    int wn = (warp >> 2) * 64;
    int g = lane >> 2, tig = lane & 3;

    const float* arow[4];
    int kq = (tid & 7) * 4;
#pragma unroll
    for (int it = 0; it < 4; it++) {
        int row = (tid >> 3) + it * 32;
        int r = m0 + row; if (r >= M) r = M - 1;
        arow[it] = g_h + (size_t)(base + r) * DFF;
    }

    float acc[2][8][4];
#pragma unroll
    for (int i = 0; i < 2; i++)
#pragma unroll
        for (int j = 0; j < 8; j++)
#pragma unroll
            for (int c = 0; c < 4; c++) acc[i][j][c] = 0.f;

    for (int k0 = 0; k0 < DFF; k0 += BK) {
#pragma unroll
        for (int it = 0; it < 4; it++) {
            int row = (tid >> 3) + it * 32;
            float4 v = *(const float4*)(arow[it] + k0 + kq);
            float4 t = make_float4(f2tf32(v.x), f2tf32(v.y), f2tf32(v.z), f2tf32(v.w));
            *(float4*)&As[row][kq] = t;
        }
#pragma unroll
        for (int it = 0; it < 4; it++) {
            int f = tid + it * 256;
            int kr = f >> 5, c4 = (f & 31) * 4;
            float4 v = *(const float4*)(W + (size_t)(k0 + kr) * DM + n0 + c4);
            float4 t = make_float4(f2tf32(v.x), f2tf32(v.y), f2tf32(v.z), f2tf32(v.w));
            *(float4*)&Bs[kr][c4] = t;
        }
        __syncthreads();
#pragma unroll
        for (int ks = 0; ks < BK; ks += 8) {
            uint32_t af[2][4];
#pragma unroll
            for (int i = 0; i < 2; i++) {
                af[i][0] = __float_as_uint(As[wm + i * 16 + g][ks + tig]);
                af[i][1] = __float_as_uint(As[wm + i * 16 + g + 8][ks + tig]);
                af[i][2] = __float_as_uint(As[wm + i * 16 + g][ks + tig + 4]);
                af[i][3] = __float_as_uint(As[wm + i * 16 + g + 8][ks + tig + 4]);
            }
            uint32_t bf[8][2];
#pragma unroll
            for (int j = 0; j < 8; j++) {
                bf[j][0] = __float_as_uint(Bs[ks + tig][wn + j * 8 + g]);
                bf[j][1] = __float_as_uint(Bs[ks + tig + 4][wn + j * 8 + g]);
            }
#pragma unroll
            for (int i = 0; i < 2; i++)
#pragma unroll
                for (int j = 0; j < 8; j++) mma_tf32(acc[i][j], af[i], bf[j]);
        }
        __syncthreads();
    }
    // epilogue: scale by combine weight -> g_y
#pragma unroll
    for (int i = 0; i < 2; i++) {
        int r0 = m0 + wm + i * 16 + g;
        int r1 = r0 + 8;
        float w0 = (r0 < M) ? g_wlist[base + r0] : 0.f;
        float w1 = (r1 < M) ? g_wlist[base + r1] : 0.f;
#pragma unroll
        for (int j = 0; j < 8; j++) {
            int col = n0 + wn + j * 8 + 2 * tig;
            if (r0 < M) {
                float* d = g_y + (size_t)(base + r0) * DM + col;
                d[0] = w0 * acc[i][j][0];
                d[1] = w0 * acc[i][j][1];
            }
            if (r1 < M) {
                float* d = g_y + (size_t)(base + r1) * DM + col;
                d[0] = w1 * acc[i][j][2];
                d[1] = w1 * acc[i][j][3];
            }
        }
    }
}

// ----------------- combine: out[t] = y[slot0] + y[slot1] -------------------
__global__ void combine_kernel(float* __restrict__ out) {
    int idx = blockIdx.x * blockDim.x + threadIdx.x;   // over TOKS*DM/4
    if (idx >= TOKS * DM / 4) return;
    int t  = idx / (DM / 4);
    int d4 = idx % (DM / 4);
    int s0 = g_slot_of[t * 2 + 0];
    int s1 = g_slot_of[t * 2 + 1];
    float4 a = *(const float4*)(g_y + (size_t)s0 * DM + d4 * 4);
    float4 b = *(const float4*)(g_y + (size_t)s1 * DM + d4 * 4);
    float4 r = make_float4(a.x + b.x, a.y + b.y, a.z + b.z, a.w + b.w);
    ((float4*)out)[idx] = r;
}

// ----------------- load-balance loss ---------------------------------------
__global__ void loss_kernel(float* __restrict__ out, int out_size) {
    __shared__ float sh[256];
    int e = threadIdx.x & 7, part = threadIdx.x >> 3;
    float s = 0.f;
    for (int b = part; b < GATE_BLOCKS; b += 32) s += g_blockprob[b * NE + e];
    sh[threadIdx.x] = s;
    __syncthreads();
    if (threadIdx.x < NE) {
        float rp = 0.f;
        for (int p = 0; p < 32; p++) rp += sh[p * NE + threadIdx.x];
        rp /= (float)TOKS;
        float usage = (float)g_count[threadIdx.x] / (float)NASSIGN;
        sh[threadIdx.x] = rp * usage;
    }
    __syncthreads();
    if (threadIdx.x == 0) {
        float loss = 0.f;
        for (int e2 = 0; e2 < NE; e2++) loss += sh[e2];
        loss *= (float)NE;
        if (out_size > TOKS * DM) out[TOKS * DM] = loss;
    }
}

// ---------------------------------------------------------------------------
extern "C" void kernel_launch(void* const* d_in, const int* in_sizes, int n_in,
                              void* d_out, int out_size)
{
    const float* x  = (const float*)d_in[0];
    const float* Wg = (const float*)d_in[1];
    const float* W1 = (const float*)d_in[2];
    const float* W2 = (const float*)d_in[3];
    float* out = (float*)d_out;

    zero_counters<<<1, 32>>>();
    gate_kernel<<<GATE_BLOCKS, 256>>>(x, Wg);
    offsets_kernel<<<1, 32>>>();
    build_kernel<<<(NASSIGN + 255) / 256, 256>>>();

    gemm1_tc<<<dim3(DFF / BN, (NASSIGN + BM - 1) / BM, NE), 256>>>(x, W1);
    gemm2_tc<<<dim3(DM / BN, (NASSIGN + BM - 1) / BM, NE), 256>>>(W2);

    combine_kernel<<<(TOKS * DM / 4 + 255) / 256, 256>>>(out);
    loss_kernel<<<1, 256>>>(out, out_size);
}

// round 4
// speedup vs baseline: 3.4251x; 1.1971x over previous
#include <cuda_runtime.h>
#include <math.h>
#include <stdint.h>

#define TOKS 8192
#define DM   1024
#define NE   8
#define DFF  4096
#define NASSIGN (TOKS * 2)
#define GATE_BLOCKS (TOKS / 8)

// ------------- scratch (static device memory; no allocations) -------------
__device__ float g_h[(size_t)NASSIGN * DFF];    // 256 MB (tf32-valued after GEMM1)
__device__ float g_y[(size_t)NASSIGN * DM];     //  64 MB
__device__ float g_w1c[(size_t)NE * DM * DFF];  // 128 MB tf32-rounded W1
__device__ float g_w2c[(size_t)NE * DFF * DM];  // 128 MB tf32-rounded W2
__device__ float g_xc[(size_t)TOKS * DM];       //  32 MB tf32-rounded x
__device__ int   g_rowlist[NASSIGN];
__device__ float g_wlist[NASSIGN];
__device__ int   g_slot_of[NASSIGN];
__device__ int   g_topi[NASSIGN];
__device__ float g_topw[NASSIGN];
__device__ int   g_count[NE];
__device__ int   g_fill[NE];
__device__ int   g_off[NE];
__device__ float g_blockprob[GATE_BLOCKS * NE];

__device__ __forceinline__ float f2tf32(float v) {
    uint32_t u;
    asm("cvt.rna.tf32.f32 %0, %1;" : "=r"(u) : "f"(v));
    return __uint_as_float(u);
}

__device__ __forceinline__ void cp_async16(void* smem, const void* gmem) {
    uint32_t s = (uint32_t)__cvta_generic_to_shared(smem);
    asm volatile("cp.async.cg.shared.global [%0], [%1], 16;" :: "r"(s), "l"(gmem));
}
#define CP_COMMIT() asm volatile("cp.async.commit_group;")
#define CP_WAIT(n)  asm volatile("cp.async.wait_group %0;" :: "n"(n))

// ---------------------------------------------------------------------------
__global__ void zero_counters() {
    int i = threadIdx.x;
    if (i < NE) { g_count[i] = 0; g_fill[i] = 0; }
}

// tf32-round all GEMM operands once (streaming, HBM-bound)
__global__ __launch_bounds__(256) void convert_kernel(
    const float* __restrict__ x, const float* __restrict__ W1,
    const float* __restrict__ W2)
{
    const size_t n1 = (size_t)NE * DM * DFF / 4;   // float4 counts
    const size_t n2 = (size_t)NE * DFF * DM / 4;
    const size_t n3 = (size_t)TOKS * DM / 4;
    size_t stride = (size_t)gridDim.x * blockDim.x;
    for (size_t i = blockIdx.x * (size_t)blockDim.x + threadIdx.x;
         i < n1 + n2 + n3; i += stride) {
        const float4* src; float4* dst; size_t j;
        if (i < n1)            { src = (const float4*)W1; dst = (float4*)g_w1c; j = i; }
        else if (i < n1 + n2)  { src = (const float4*)W2; dst = (float4*)g_w2c; j = i - n1; }
        else                   { src = (const float4*)x;  dst = (float4*)g_xc;  j = i - n1 - n2; }
        float4 v = src[j];
        dst[j] = make_float4(f2tf32(v.x), f2tf32(v.y), f2tf32(v.z), f2tf32(v.w));
    }
}

// One warp per token; 8 warps (8 tokens) per block.
__global__ __launch_bounds__(256) void gate_kernel(
    const float* __restrict__ x, const float* __restrict__ Wg)
{
    int warp = threadIdx.x >> 5, lane = threadIdx.x & 31;
    int t = blockIdx.x * 8 + warp;
    __shared__ float probs_sh[8][NE];

    float acc[NE];
#pragma unroll
    for (int e = 0; e < NE; e++) acc[e] = 0.f;
    const float* xr = x + (size_t)t * DM;
    for (int i = lane; i < DM; i += 32) {
        float xv = xr[i];
#pragma unroll
        for (int e = 0; e < NE; e++) acc[e] += xv * Wg[i * NE + e];
    }
#pragma unroll
    for (int off = 16; off; off >>= 1)
#pragma unroll
        for (int e = 0; e < NE; e++)
            acc[e] += __shfl_xor_sync(0xFFFFFFFFu, acc[e], off);

    if (lane == 0) {
        float mx = acc[0];
#pragma unroll
        for (int e = 1; e < NE; e++) mx = fmaxf(mx, acc[e]);
        float p[NE], s = 0.f;
#pragma unroll
        for (int e = 0; e < NE; e++) { p[e] = __expf(acc[e] - mx); s += p[e]; }
        float inv = 1.f / s;
#pragma unroll
        for (int e = 0; e < NE; e++) p[e] *= inv;
        int i0 = 0;
#pragma unroll
        for (int e = 1; e < NE; e++) if (p[e] > p[i0]) i0 = e;
        int i1 = (i0 == 0) ? 1 : 0;
#pragma unroll
        for (int e = 0; e < NE; e++) if (e != i0 && p[e] > p[i1]) i1 = e;
        float v0 = p[i0], v1 = p[i1];
        float s2 = 1.f / (v0 + v1 + 1e-8f);
        g_topi[t * 2 + 0] = i0;  g_topw[t * 2 + 0] = v0 * s2;
        g_topi[t * 2 + 1] = i1;  g_topw[t * 2 + 1] = v1 * s2;
        atomicAdd(&g_count[i0], 1);
        atomicAdd(&g_count[i1], 1);
#pragma unroll
        for (int e = 0; e < NE; e++) probs_sh[warp][e] = p[e];
    }
    __syncthreads();
    if (threadIdx.x < NE) {
        float s = 0.f;
#pragma unroll
        for (int w = 0; w < 8; w++) s += probs_sh[w][threadIdx.x];
        g_blockprob[blockIdx.x * NE + threadIdx.x] = s;
    }
}

__global__ void offsets_kernel() {
    if (threadIdx.x == 0) {
        int o = 0;
        for (int e = 0; e < NE; e++) { g_off[e] = o; o += g_count[e]; }
    }
}

__global__ void build_kernel() {
    int a = blockIdx.x * blockDim.x + threadIdx.x;
    if (a >= NASSIGN) return;
    int e = g_topi[a];
    int pos = atomicAdd(&g_fill[e], 1);
    int slot = g_off[e] + pos;
    g_rowlist[slot] = a >> 1;
    g_wlist[slot] = g_topw[a];
    g_slot_of[a] = slot;
}

// ======================= tf32 tensor-core GEMMs ============================
// 128x128x32 block tile, 256 threads = 8 warps, warp tile 32x64 via
// mma.sync.m16n8k8.tf32. 2-stage cp.async double-buffered pipeline.
// All operand pointers resolved in DEVICE code (device globals).

__device__ __forceinline__ void mma_tf32(float* c, const uint32_t* a, const uint32_t* b) {
    asm volatile(
        "mma.sync.aligned.m16n8k8.row.col.f32.tf32.tf32.f32 "
        "{%0,%1,%2,%3}, {%4,%5,%6,%7}, {%8,%9}, {%0,%1,%2,%3};"
        : "+f"(c[0]), "+f"(c[1]), "+f"(c[2]), "+f"(c[3])
        : "r"(a[0]), "r"(a[1]), "r"(a[2]), "r"(a[3]), "r"(b[0]), "r"(b[1]));
}

#define BM 128
#define BN 128
#define BK 32
#define A_STRIDE 36   // As row stride in floats (pad 4) -> 144B, 16B-multiple
#define B_STRIDE 136  // Bs row stride in floats (pad 8) -> 544B, 16B-multiple
#define A_TILE (BM * A_STRIDE)
#define B_TILE (BK * B_STRIDE)
#define SMEM_FLOATS (2 * (A_TILE + B_TILE))
#define SMEM_BYTES (SMEM_FLOATS * 4)

// GELU_OUT=true: GEMM1 (A=g_xc gathered, B=g_w1c, out=gelu->g_h)
// GELU_OUT=false: GEMM2 (A=g_h, B=g_w2c, out=w*acc->g_y)
template<int KDIM, int NDIM, bool GELU_OUT>
__global__ __launch_bounds__(256, 2) void gemm_tc()
{
    extern __shared__ float sm[];
    float* As = sm;                       // [2][BM][A_STRIDE]
    float* Bs = sm + 2 * A_TILE;          // [2][BK][B_STRIDE]

    int e = blockIdx.z;
    int M = g_count[e];
    int m0 = blockIdx.y * BM;
    if (m0 >= M) return;
    int n0 = blockIdx.x * BN;
    int base = g_off[e];
    const float* W = (GELU_OUT ? g_w1c : g_w2c) + (size_t)e * KDIM * NDIM;

    int tid = threadIdx.x;
    int lane = tid & 31, warp = tid >> 5;
    int wm = (warp & 3) * 32;
    int wn = (warp >> 2) * 64;
    int g = lane >> 2, tig = lane & 3;

    // gathered A-row pointers (clamped; duplicate rows beyond M are unused)
    const float* arow[4];
    int kq = (tid & 7) * 4;
#pragma unroll
    for (int it = 0; it < 4; it++) {
        int r = m0 + (tid >> 3) + it * 32; if (r >= M) r = M - 1;
        arow[it] = GELU_OUT ? (g_xc + (size_t)g_rowlist[base + r] * KDIM)
                            : (g_h + (size_t)(base + r) * KDIM);
    }

    float acc[2][8][4];
#pragma unroll
    for (int i = 0; i < 2; i++)
#pragma unroll
        for (int j = 0; j < 8; j++)
#pragma unroll
            for (int c = 0; c < 4; c++) acc[i][j][c] = 0.f;

    const int NT = KDIM / BK;
    int arow_off = (tid >> 3) * A_STRIDE + kq;
    int b_kr = tid >> 5, b_c4 = (tid & 31) * 4;

    // prefetch tile 0 into stage 0
    {
#pragma unroll
        for (int it = 0; it < 4; it++)
            cp_async16(As + arow_off + it * 32 * A_STRIDE, arow[it] + kq);
#pragma unroll
        for (int it = 0; it < 4; it++)
            cp_async16(Bs + (b_kr + it * 8) * B_STRIDE + b_c4,
                       W + (size_t)(b_kr + it * 8) * NDIM + n0 + b_c4);
        CP_COMMIT();
    }

    for (int kt = 0; kt < NT; kt++) {
        int cur = kt & 1;
        if (kt + 1 < NT) {
            int nxt = cur ^ 1;
            int k0 = (kt + 1) * BK;
            float* A1 = As + nxt * A_TILE;
            float* B1 = Bs + nxt * B_TILE;
#pragma unroll
            for (int it = 0; it < 4; it++)
                cp_async16(A1 + arow_off + it * 32 * A_STRIDE, arow[it] + k0 + kq);
#pragma unroll
            for (int it = 0; it < 4; it++)
                cp_async16(B1 + (b_kr + it * 8) * B_STRIDE + b_c4,
                           W + (size_t)(k0 + b_kr + it * 8) * NDIM + n0 + b_c4);
            CP_COMMIT();
            CP_WAIT(1);
        } else {
            CP_WAIT(0);
        }
        __syncthreads();

        const float* Ac = As + cur * A_TILE;
        const float* Bc = Bs + cur * B_TILE;
#pragma unroll
        for (int ks = 0; ks < BK; ks += 8) {
            uint32_t af[2][4];
#pragma unroll
            for (int i = 0; i < 2; i++) {
                const float* ar = Ac + (wm + i * 16 + g) * A_STRIDE + ks + tig;
                af[i][0] = __float_as_uint(ar[0]);
                af[i][1] = __float_as_uint(ar[8 * A_STRIDE]);
                af[i][2] = __float_as_uint(ar[4]);
                af[i][3] = __float_as_uint(ar[8 * A_STRIDE + 4]);
            }
            uint32_t bf[8][2];
#pragma unroll
            for (int j = 0; j < 8; j++) {
                const float* br = Bc + (ks + tig) * B_STRIDE + wn + j * 8 + g;
                bf[j][0] = __float_as_uint(br[0]);
                bf[j][1] = __float_as_uint(br[4 * B_STRIDE]);
            }
#pragma unroll
            for (int i = 0; i < 2; i++)
#pragma unroll
                for (int j = 0; j < 8; j++) mma_tf32(acc[i][j], af[i], bf[j]);
        }
        __syncthreads();
    }

    // epilogue
#pragma unroll
    for (int i = 0; i < 2; i++) {
        int r0 = m0 + wm + i * 16 + g;
        int r1 = r0 + 8;
        if (GELU_OUT) {
#pragma unroll
            for (int j = 0; j < 8; j++) {
                int col = n0 + wn + j * 8 + 2 * tig;
                if (r0 < M) {
                    float* d = g_h + (size_t)(base + r0) * NDIM + col;
                    float v0 = acc[i][j][0], v1 = acc[i][j][1];
                    d[0] = f2tf32(0.5f * v0 * (1.0f + erff(v0 * 0.70710678118654752f)));
                    d[1] = f2tf32(0.5f * v1 * (1.0f + erff(v1 * 0.70710678118654752f)));
                }
                if (r1 < M) {
                    float* d = g_h + (size_t)(base + r1) * NDIM + col;
                    float v2 = acc[i][j][2], v3 = acc[i][j][3];
                    d[0] = f2tf32(0.5f * v2 * (1.0f + erff(v2 * 0.70710678118654752f)));
                    d[1] = f2tf32(0.5f * v3 * (1.0f + erff(v3 * 0.70710678118654752f)));
                }
            }
        } else {
            float w0 = (r0 < M) ? g_wlist[base + r0] : 0.f;
            float w1 = (r1 < M) ? g_wlist[base + r1] : 0.f;
#pragma unroll
            for (int j = 0; j < 8; j++) {
                int col = n0 + wn + j * 8 + 2 * tig;
                if (r0 < M) {
                    float* d = g_y + (size_t)(base + r0) * NDIM + col;
                    d[0] = w0 * acc[i][j][0];
                    d[1] = w0 * acc[i][j][1];
                }
                if (r1 < M) {
                    float* d = g_y + (size_t)(base + r1) * NDIM + col;
                    d[0] = w1 * acc[i][j][2];
                    d[1] = w1 * acc[i][j][3];
                }
            }
        }
    }
}

// ----------------- combine: out[t] = y[slot0] + y[slot1] -------------------
__global__ void combine_kernel(float* __restrict__ out) {
    int idx = blockIdx.x * blockDim.x + threadIdx.x;
    if (idx >= TOKS * DM / 4) return;
    int t  = idx / (DM / 4);
    int d4 = idx % (DM / 4);
    int s0 = g_slot_of[t * 2 + 0];
    int s1 = g_slot_of[t * 2 + 1];
    float4 a = *(const float4*)(g_y + (size_t)s0 * DM + d4 * 4);
    float4 b = *(const float4*)(g_y + (size_t)s1 * DM + d4 * 4);
    ((float4*)out)[idx] = make_float4(a.x + b.x, a.y + b.y, a.z + b.z, a.w + b.w);
}

// ----------------- load-balance loss ---------------------------------------
__global__ void loss_kernel(float* __restrict__ out, int out_size) {
    __shared__ float sh[256];
    int e = threadIdx.x & 7, part = threadIdx.x >> 3;
    float s = 0.f;
    for (int b = part; b < GATE_BLOCKS; b += 32) s += g_blockprob[b * NE + e];
    sh[threadIdx.x] = s;
    __syncthreads();
    if (threadIdx.x < NE) {
        float rp = 0.f;
        for (int p = 0; p < 32; p++) rp += sh[p * NE + threadIdx.x];
        rp /= (float)TOKS;
        float usage = (float)g_count[threadIdx.x] / (float)NASSIGN;
        sh[threadIdx.x] = rp * usage;
    }
    __syncthreads();
    if (threadIdx.x == 0) {
        float loss = 0.f;
        for (int e2 = 0; e2 < NE; e2++) loss += sh[e2];
        loss *= (float)NE;
        if (out_size > TOKS * DM) out[TOKS * DM] = loss;
    }
}

// ---------------------------------------------------------------------------
extern "C" void kernel_launch(void* const* d_in, const int* in_sizes, int n_in,
                              void* d_out, int out_size)
{
    const float* x  = (const float*)d_in[0];
    const float* Wg = (const float*)d_in[1];
    const float* W1 = (const float*)d_in[2];
    const float* W2 = (const float*)d_in[3];
    float* out = (float*)d_out;

    static int attr_done = 0;
    if (!attr_done) {
        cudaFuncSetAttribute(gemm_tc<DM, DFF, true>,
                             cudaFuncAttributeMaxDynamicSharedMemorySize, SMEM_BYTES);
        cudaFuncSetAttribute(gemm_tc<DFF, DM, false>,
                             cudaFuncAttributeMaxDynamicSharedMemorySize, SMEM_BYTES);
        attr_done = 1;
    }

    zero_counters<<<1, 32>>>();
    convert_kernel<<<1184, 256>>>(x, W1, W2);
    gate_kernel<<<GATE_BLOCKS, 256>>>(x, Wg);
    offsets_kernel<<<1, 32>>>();
    build_kernel<<<(NASSIGN + 255) / 256, 256>>>();

    gemm_tc<DM, DFF, true><<<dim3(DFF / BN, (NASSIGN + BM - 1) / BM, NE), 256, SMEM_BYTES>>>();
    gemm_tc<DFF, DM, false><<<dim3(DM / BN, (NASSIGN + BM - 1) / BM, NE), 256, SMEM_BYTES>>>();

    combine_kernel<<<(TOKS * DM / 4 + 255) / 256, 256>>>(out);
    loss_kernel<<<1, 256>>>(out, out_size);
}

// round 9
// speedup vs baseline: 3.4374x; 1.0036x over previous
#include <cuda_runtime.h>
#include <math.h>
#include <stdint.h>

#define TOKS 8192
#define DM   1024
#define NE   8
#define DFF  4096
#define NASSIGN (TOKS * 2)
#define GATE_BLOCKS (TOKS / 8)

// ------------- scratch (static device memory; no allocations) -------------
__device__ float g_h[(size_t)NASSIGN * DFF];    // 256 MB (tf32-valued after GEMM1)
__device__ float g_y[(size_t)NASSIGN * DM];     //  64 MB
__device__ float g_w1c[(size_t)NE * DM * DFF];  // 128 MB tf32-rounded W1
__device__ float g_w2c[(size_t)NE * DFF * DM];  // 128 MB tf32-rounded W2
__device__ float g_xc[(size_t)TOKS * DM];       //  32 MB tf32-rounded x
__device__ int   g_rowlist[NASSIGN];
__device__ float g_wlist[NASSIGN];
__device__ int   g_slot_of[NASSIGN];
__device__ int   g_topi[NASSIGN];
__device__ float g_topw[NASSIGN];
__device__ int   g_count[NE];
__device__ int   g_fill[NE];
__device__ int   g_off[NE];
__device__ float g_blockprob[GATE_BLOCKS * NE];

__device__ __forceinline__ float f2tf32(float v) {
    uint32_t u;
    asm("cvt.rna.tf32.f32 %0, %1;" : "=r"(u) : "f"(v));
    return __uint_as_float(u);
}

__device__ __forceinline__ void cp_async16(void* smem, const void* gmem) {
    uint32_t s = (uint32_t)__cvta_generic_to_shared(smem);
    asm volatile("cp.async.cg.shared.global [%0], [%1], 16;" :: "r"(s), "l"(gmem));
}
#define CP_COMMIT() asm volatile("cp.async.commit_group;")
#define CP_WAIT(n)  asm volatile("cp.async.wait_group %0;" :: "n"(n))

// ---------------------------------------------------------------------------
__global__ void zero_counters() {
    int i = threadIdx.x;
    if (i < NE) { g_count[i] = 0; g_fill[i] = 0; }
}

// tf32-round all GEMM operands once (streaming, HBM-bound)
__global__ __launch_bounds__(256) void convert_kernel(
    const float* __restrict__ x, const float* __restrict__ W1,
    const float* __restrict__ W2)
{
    const size_t n1 = (size_t)NE * DM * DFF / 4;   // float4 counts
    const size_t n2 = (size_t)NE * DFF * DM / 4;
    const size_t n3 = (size_t)TOKS * DM / 4;
    size_t stride = (size_t)gridDim.x * blockDim.x;
    for (size_t i = blockIdx.x * (size_t)blockDim.x + threadIdx.x;
         i < n1 + n2 + n3; i += stride) {
        const float4* src; float4* dst; size_t j;
        if (i < n1)            { src = (const float4*)W1; dst = (float4*)g_w1c; j = i; }
        else if (i < n1 + n2)  { src = (const float4*)W2; dst = (float4*)g_w2c; j = i - n1; }
        else                   { src = (const float4*)x;  dst = (float4*)g_xc;  j = i - n1 - n2; }
        float4 v = src[j];
        dst[j] = make_float4(f2tf32(v.x), f2tf32(v.y), f2tf32(v.z), f2tf32(v.w));
    }
}

// One warp per token; 8 warps (8 tokens) per block.
__global__ __launch_bounds__(256) void gate_kernel(
    const float* __restrict__ x, const float* __restrict__ Wg)
{
    int warp = threadIdx.x >> 5, lane = threadIdx.x & 31;
    int t = blockIdx.x * 8 + warp;
    __shared__ float probs_sh[8][NE];

    float acc[NE];
#pragma unroll
    for (int e = 0; e < NE; e++) acc[e] = 0.f;
    const float* xr = x + (size_t)t * DM;
    for (int i = lane; i < DM; i += 32) {
        float xv = xr[i];
#pragma unroll
        for (int e = 0; e < NE; e++) acc[e] += xv * Wg[i * NE + e];
    }
#pragma unroll
    for (int off = 16; off; off >>= 1)
#pragma unroll
        for (int e = 0; e < NE; e++)
            acc[e] += __shfl_xor_sync(0xFFFFFFFFu, acc[e], off);

    if (lane == 0) {
        float mx = acc[0];
#pragma unroll
        for (int e = 1; e < NE; e++) mx = fmaxf(mx, acc[e]);
        float p[NE], s = 0.f;
#pragma unroll
        for (int e = 0; e < NE; e++) { p[e] = __expf(acc[e] - mx); s += p[e]; }
        float inv = 1.f / s;
#pragma unroll
        for (int e = 0; e < NE; e++) p[e] *= inv;
        int i0 = 0;
#pragma unroll
        for (int e = 1; e < NE; e++) if (p[e] > p[i0]) i0 = e;
        int i1 = (i0 == 0) ? 1 : 0;
#pragma unroll
        for (int e = 0; e < NE; e++) if (e != i0 && p[e] > p[i1]) i1 = e;
        float v0 = p[i0], v1 = p[i1];
        float s2 = 1.f / (v0 + v1 + 1e-8f);
        g_topi[t * 2 + 0] = i0;  g_topw[t * 2 + 0] = v0 * s2;
        g_topi[t * 2 + 1] = i1;  g_topw[t * 2 + 1] = v1 * s2;
        atomicAdd(&g_count[i0], 1);
        atomicAdd(&g_count[i1], 1);
#pragma unroll
        for (int e = 0; e < NE; e++) probs_sh[warp][e] = p[e];
    }
    __syncthreads();
    if (threadIdx.x < NE) {
        float s = 0.f;
#pragma unroll
        for (int w = 0; w < 8; w++) s += probs_sh[w][threadIdx.x];
        g_blockprob[blockIdx.x * NE + threadIdx.x] = s;
    }
}

__global__ void offsets_kernel() {
    if (threadIdx.x == 0) {
        int o = 0;
        for (int e = 0; e < NE; e++) { g_off[e] = o; o += g_count[e]; }
    }
}

__global__ void build_kernel() {
    int a = blockIdx.x * blockDim.x + threadIdx.x;
    if (a >= NASSIGN) return;
    int e = g_topi[a];
    int pos = atomicAdd(&g_fill[e], 1);
    int slot = g_off[e] + pos;
    g_rowlist[slot] = a >> 1;
    g_wlist[slot] = g_topw[a];
    g_slot_of[a] = slot;
}

// ======================= tf32 tensor-core GEMMs ============================
// 128x128x32 block tile, 256 threads = 8 warps, warp tile 32x64 via
// mma.sync.m16n8k8.tf32. 3-stage cp.async ring, ONE __syncthreads per tile.
// All operand pointers resolved in DEVICE code (device globals).

__device__ __forceinline__ void mma_tf32(float* c, const uint32_t* a, const uint32_t* b) {
    asm volatile(
        "mma.sync.aligned.m16n8k8.row.col.f32.tf32.tf32.f32 "
        "{%0,%1,%2,%3}, {%4,%5,%6,%7}, {%8,%9}, {%0,%1,%2,%3};"
        : "+f"(c[0]), "+f"(c[1]), "+f"(c[2]), "+f"(c[3])
        : "r"(a[0]), "r"(a[1]), "r"(a[2]), "r"(a[3]), "r"(b[0]), "r"(b[1]));
}

#define BM 128
#define BN 128
#define BK 32
#define NST 3
#define A_STRIDE 36   // As row stride in floats (pad 4) -> 144B, 16B-multiple
#define B_STRIDE 136  // Bs row stride in floats (pad 8) -> 544B, 16B-multiple
#define A_TILE (BM * A_STRIDE)
#define B_TILE (BK * B_STRIDE)
#define SMEM_FLOATS (NST * (A_TILE + B_TILE))
#define SMEM_BYTES (SMEM_FLOATS * 4)

// GELU_OUT=true: GEMM1 (A=g_xc gathered, B=g_w1c, out=gelu->g_h)
// GELU_OUT=false: GEMM2 (A=g_h, B=g_w2c, out=w*acc->g_y)
template<int KDIM, int NDIM, bool GELU_OUT>
__global__ __launch_bounds__(256, 2) void gemm_tc()
{
    extern __shared__ float sm[];
    float* As = sm;                         // [NST][BM][A_STRIDE]
    float* Bs = sm + NST * A_TILE;          // [NST][BK][B_STRIDE]

    int e = blockIdx.z;
    int M = g_count[e];
    int m0 = blockIdx.y * BM;
    if (m0 >= M) return;
    int n0 = blockIdx.x * BN;
    int base = g_off[e];
    const float* W = (GELU_OUT ? g_w1c : g_w2c) + (size_t)e * KDIM * NDIM;

    int tid = threadIdx.x;
    int lane = tid & 31, warp = tid >> 5;
    int wm = (warp & 3) * 32;
    int wn = (warp >> 2) * 64;
    int g = lane >> 2, tig = lane & 3;

    // gathered A-row pointers (clamped; duplicate rows beyond M are unused)
    const float* arow[4];
    int kq = (tid & 7) * 4;
#pragma unroll
    for (int it = 0; it < 4; it++) {
        int r = m0 + (tid >> 3) + it * 32; if (r >= M) r = M - 1;
        arow[it] = GELU_OUT ? (g_xc + (size_t)g_rowlist[base + r] * KDIM)
                            : (g_h + (size_t)(base + r) * KDIM);
    }

    float acc[2][8][4];
#pragma unroll
    for (int i = 0; i < 2; i++)
#pragma unroll
        for (int j = 0; j < 8; j++)
#pragma unroll
            for (int c = 0; c < 4; c++) acc[i][j][c] = 0.f;

    const int NT = KDIM / BK;
    int arow_off = (tid >> 3) * A_STRIDE + kq;
    int b_kr = tid >> 5, b_c4 = (tid & 31) * 4;

#define LOAD_STAGE(ti, s) do {                                              \
        float* A1 = As + (s) * A_TILE;                                      \
        float* B1 = Bs + (s) * B_TILE;                                      \
        int k0_ = (ti) * BK;                                                \
        _Pragma("unroll")                                                   \
        for (int it = 0; it < 4; it++)                                      \
            cp_async16(A1 + arow_off + it * 32 * A_STRIDE, arow[it] + k0_ + kq); \
        _Pragma("unroll")                                                   \
        for (int it = 0; it < 4; it++)                                      \
            cp_async16(B1 + (b_kr + it * 8) * B_STRIDE + b_c4,              \
                       W + (size_t)(k0_ + b_kr + it * 8) * NDIM + n0 + b_c4); \
        CP_COMMIT();                                                        \
    } while (0)

    // prefetch tiles 0,1 into stages 0,1
    LOAD_STAGE(0, 0);
    LOAD_STAGE(1, 1);

    for (int kt = 0; kt < NT; kt++) {
        int cur = kt % NST;
        // commits issued so far = kt+2 (tiles 0..kt+1); need tile kt complete
        if (kt < NT - 1) CP_WAIT(1);
        else             CP_WAIT(0);
        __syncthreads();   // all warps done reading stage (kt-1)%NST
        if (kt + 2 < NT) LOAD_STAGE(kt + 2, (kt + 2) % NST);

        const float* Ac = As + cur * A_TILE;
        const float* Bc = Bs + cur * B_TILE;
#pragma unroll
        for (int ks = 0; ks < BK; ks += 8) {
            uint32_t af[2][4];
#pragma unroll
            for (int i = 0; i < 2; i++) {
                const float* ar = Ac + (wm + i * 16 + g) * A_STRIDE + ks + tig;
                af[i][0] = __float_as_uint(ar[0]);
                af[i][1] = __float_as_uint(ar[8 * A_STRIDE]);
                af[i][2] = __float_as_uint(ar[4]);
                af[i][3] = __float_as_uint(ar[8 * A_STRIDE + 4]);
            }
            uint32_t bf[8][2];
#pragma unroll
            for (int j = 0; j < 8; j++) {
                const float* br = Bc + (ks + tig) * B_STRIDE + wn + j * 8 + g;
                bf[j][0] = __float_as_uint(br[0]);
                bf[j][1] = __float_as_uint(br[4 * B_STRIDE]);
            }
#pragma unroll
            for (int i = 0; i < 2; i++)
#pragma unroll
                for (int j = 0; j < 8; j++) mma_tf32(acc[i][j], af[i], bf[j]);
        }
    }

    // epilogue
#pragma unroll
    for (int i = 0; i < 2; i++) {
        int r0 = m0 + wm + i * 16 + g;
        int r1 = r0 + 8;
        if (GELU_OUT) {
#pragma unroll
            for (int j = 0; j < 8; j++) {
                int col = n0 + wn + j * 8 + 2 * tig;
                if (r0 < M) {
                    float* d = g_h + (size_t)(base + r0) * NDIM + col;
                    float v0 = acc[i][j][0], v1 = acc[i][j][1];
                    d[0] = f2tf32(0.5f * v0 * (1.0f + erff(v0 * 0.70710678118654752f)));
                    d[1] = f2tf32(0.5f * v1 * (1.0f + erff(v1 * 0.70710678118654752f)));
                }
                if (r1 < M) {
                    float* d = g_h + (size_t)(base + r1) * NDIM + col;
                    float v2 = acc[i][j][2], v3 = acc[i][j][3];
                    d[0] = f2tf32(0.5f * v2 * (1.0f + erff(v2 * 0.70710678118654752f)));
                    d[1] = f2tf32(0.5f * v3 * (1.0f + erff(v3 * 0.70710678118654752f)));
                }
            }
        } else {
            float w0 = (r0 < M) ? g_wlist[base + r0] : 0.f;
            float w1 = (r1 < M) ? g_wlist[base + r1] : 0.f;
#pragma unroll
            for (int j = 0; j < 8; j++) {
                int col = n0 + wn + j * 8 + 2 * tig;
                if (r0 < M) {
                    float* d = g_y + (size_t)(base + r0) * NDIM + col;
                    d[0] = w0 * acc[i][j][0];
                    d[1] = w0 * acc[i][j][1];
                }
                if (r1 < M) {
                    float* d = g_y + (size_t)(base + r1) * NDIM + col;
                    d[0] = w1 * acc[i][j][2];
                    d[1] = w1 * acc[i][j][3];
                }
            }
        }
    }
}

// ----------------- combine: out[t] = y[slot0] + y[slot1] -------------------
__global__ void combine_kernel(float* __restrict__ out) {
    int idx = blockIdx.x * blockDim.x + threadIdx.x;
    if (idx >= TOKS * DM / 4) return;
    int t  = idx / (DM / 4);
    int d4 = idx % (DM / 4);
    int s0 = g_slot_of[t * 2 + 0];
    int s1 = g_slot_of[t * 2 + 1];
    float4 a = *(const float4*)(g_y + (size_t)s0 * DM + d4 * 4);
    float4 b = *(const float4*)(g_y + (size_t)s1 * DM + d4 * 4);
    ((float4*)out)[idx] = make_float4(a.x + b.x, a.y + b.y, a.z + b.z, a.w + b.w);
}

// ----------------- load-balance loss ---------------------------------------
__global__ void loss_kernel(float* __restrict__ out, int out_size) {
    __shared__ float sh[256];
    int e = threadIdx.x & 7, part = threadIdx.x >> 3;
    float s = 0.f;
    for (int b = part; b < GATE_BLOCKS; b += 32) s += g_blockprob[b * NE + e];
    sh[threadIdx.x] = s;
    __syncthreads();
    if (threadIdx.x < NE) {
        float rp = 0.f;
        for (int p = 0; p < 32; p++) rp += sh[p * NE + threadIdx.x];
        rp /= (float)TOKS;
        float usage = (float)g_count[threadIdx.x] / (float)NASSIGN;
        sh[threadIdx.x] = rp * usage;
    }
    __syncthreads();
    if (threadIdx.x == 0) {
        float loss = 0.f;
        for (int e2 = 0; e2 < NE; e2++) loss += sh[e2];
        loss *= (float)NE;
        if (out_size > TOKS * DM) out[TOKS * DM] = loss;
    }
}

// ---------------------------------------------------------------------------
extern "C" void kernel_launch(void* const* d_in, const int* in_sizes, int n_in,
                              void* d_out, int out_size)
{
    const float* x  = (const float*)d_in[0];
    const float* Wg = (const float*)d_in[1];
    const float* W1 = (const float*)d_in[2];
    const float* W2 = (const float*)d_in[3];
    float* out = (float*)d_out;

    cudaFuncSetAttribute(gemm_tc<DM, DFF, true>,
                         cudaFuncAttributeMaxDynamicSharedMemorySize, SMEM_BYTES);
    cudaFuncSetAttribute(gemm_tc<DFF, DM, false>,
                         cudaFuncAttributeMaxDynamicSharedMemorySize, SMEM_BYTES);

    zero_counters<<<1, 32>>>();
    convert_kernel<<<1184, 256>>>(x, W1, W2);
    gate_kernel<<<GATE_BLOCKS, 256>>>(x, Wg);
    offsets_kernel<<<1, 32>>>();
    build_kernel<<<(NASSIGN + 255) / 256, 256>>>();

    gemm_tc<DM, DFF, true><<<dim3(DFF / BN, NASSIGN / BM, NE), 256, SMEM_BYTES>>>();
    gemm_tc<DFF, DM, false><<<dim3(DM / BN, NASSIGN / BM, NE), 256, SMEM_BYTES>>>();

    combine_kernel<<<(TOKS * DM / 4 + 255) / 256, 256>>>(out);
    loss_kernel<<<1, 256>>>(out, out_size);
}

// round 11
// speedup vs baseline: 5.0678x; 1.4743x over previous
#include <cuda_runtime.h>
#include <cuda_fp16.h>
#include <math.h>
#include <stdint.h>

#define TOKS 8192
#define DM   1024
#define NE   8
#define DFF  4096
#define NASSIGN (TOKS * 2)
#define GATE_BLOCKS (TOKS / 8)

// ------------- scratch (static device memory; no allocations) -------------
// RULE: no g_* symbol may EVER be passed as a kernel <<<>>> argument (host
// code sees the shadow symbol, not the device address). Resolve in device code.
__device__ __align__(256) __half g_h[(size_t)NASSIGN * DFF];     // 128 MB
__device__ float  g_y[(size_t)NASSIGN * DM];                     //  64 MB
__device__ __align__(256) __half g_w1h[(size_t)NE * DM * DFF];   //  64 MB W1^T [e][n][k]
__device__ __align__(256) __half g_w2h[(size_t)NE * DFF * DM];   //  64 MB W2^T [e][n][k]
__device__ __align__(256) __half g_xh[(size_t)TOKS * DM];        //  16 MB
__device__ int    g_rowlist[NASSIGN];
__device__ float  g_wlist[NASSIGN];
__device__ int    g_slot_of[NASSIGN];
__device__ int    g_topi[NASSIGN];
__device__ float  g_topw[NASSIGN];
__device__ int    g_count[NE];
__device__ int    g_fill[NE];
__device__ int    g_off[NE];
__device__ float  g_blockprob[GATE_BLOCKS * NE];

// ----------------------------- helpers --------------------------------
__device__ __forceinline__ void cp16(void* smem, const void* gmem) {
    uint32_t s = (uint32_t)__cvta_generic_to_shared(smem);
    asm volatile("cp.async.cg.shared.global [%0], [%1], 16;" :: "r"(s), "l"(gmem));
}
#define CP_COMMIT() asm volatile("cp.async.commit_group;")
#define CP_WAIT(n)  asm volatile("cp.async.wait_group %0;" :: "n"(n))

__device__ __forceinline__ void mma_fp16(float* c, const uint32_t* a, const uint32_t* b) {
    asm volatile(
        "mma.sync.aligned.m16n8k16.row.col.f32.f16.f16.f32 "
        "{%0,%1,%2,%3}, {%4,%5,%6,%7}, {%8,%9}, {%0,%1,%2,%3};"
        : "+f"(c[0]), "+f"(c[1]), "+f"(c[2]), "+f"(c[3])
        : "r"(a[0]), "r"(a[1]), "r"(a[2]), "r"(a[3]), "r"(b[0]), "r"(b[1]));
}

// ---------------------------------------------------------------------------
__global__ void zero_counters() {
    int i = threadIdx.x;
    if (i < NE) { g_count[i] = 0; g_fill[i] = 0; }
}

// x (fp32) -> g_xh (fp16)
__global__ __launch_bounds__(256) void convert_x(const float* __restrict__ x) {
    size_t i = blockIdx.x * (size_t)blockDim.x + threadIdx.x;
    if (i >= (size_t)TOKS * DM / 4) return;
    float4 v = ((const float4*)x)[i];
    __half2 h0 = __floats2half2_rn(v.x, v.y);
    __half2 h1 = __floats2half2_rn(v.z, v.w);
    uint2 o; o.x = *(uint32_t*)&h0; o.y = *(uint32_t*)&h1;
    ((uint2*)g_xh)[i] = o;
}

// W[e][K][N] fp32 -> g_w{1,2}h[e][N][K] fp16; destination resolved in DEVICE code.
template<bool IS_W1>
__global__ __launch_bounds__(256) void transpose_convert(const float* __restrict__ W)
{
    const int K = IS_W1 ? DM : DFF;
    const int N = IS_W1 ? DFF : DM;
    __half* Wt = IS_W1 ? g_w1h : g_w2h;

    __shared__ float t[32][33];
    int e = blockIdx.z;
    int k0 = blockIdx.y * 32, n0 = blockIdx.x * 32;
    const float* src = W + (size_t)e * K * N;
    __half* dst = Wt + (size_t)e * K * N;
    int tx = threadIdx.x & 31, ty = threadIdx.x >> 5;  // 32 x 8
#pragma unroll
    for (int r = 0; r < 4; r++)
        t[ty * 4 + r][tx] = src[(size_t)(k0 + ty * 4 + r) * N + n0 + tx];
    __syncthreads();
#pragma unroll
    for (int r = 0; r < 4; r++)
        dst[(size_t)(n0 + ty * 4 + r) * K + k0 + tx] = __float2half_rn(t[tx][ty * 4 + r]);
}

// One warp per token; 8 warps (8 tokens) per block.
__global__ __launch_bounds__(256) void gate_kernel(
    const float* __restrict__ x, const float* __restrict__ Wg)
{
    int warp = threadIdx.x >> 5, lane = threadIdx.x & 31;
    int t = blockIdx.x * 8 + warp;
    __shared__ float probs_sh[8][NE];

    float acc[NE];
#pragma unroll
    for (int e = 0; e < NE; e++) acc[e] = 0.f;
    const float* xr = x + (size_t)t * DM;
    for (int i = lane; i < DM; i += 32) {
        float xv = xr[i];
#pragma unroll
        for (int e = 0; e < NE; e++) acc[e] += xv * Wg[i * NE + e];
    }
#pragma unroll
    for (int off = 16; off; off >>= 1)
#pragma unroll
        for (int e = 0; e < NE; e++)
            acc[e] += __shfl_xor_sync(0xFFFFFFFFu, acc[e], off);

    if (lane == 0) {
        float mx = acc[0];
#pragma unroll
        for (int e = 1; e < NE; e++) mx = fmaxf(mx, acc[e]);
        float p[NE], s = 0.f;
#pragma unroll
        for (int e = 0; e < NE; e++) { p[e] = __expf(acc[e] - mx); s += p[e]; }
        float inv = 1.f / s;
#pragma unroll
        for (int e = 0; e < NE; e++) p[e] *= inv;
        int i0 = 0;
#pragma unroll
        for (int e = 1; e < NE; e++) if (p[e] > p[i0]) i0 = e;
        int i1 = (i0 == 0) ? 1 : 0;
#pragma unroll
        for (int e = 0; e < NE; e++) if (e != i0 && p[e] > p[i1]) i1 = e;
        float v0 = p[i0], v1 = p[i1];
        float s2 = 1.f / (v0 + v1 + 1e-8f);
        g_topi[t * 2 + 0] = i0;  g_topw[t * 2 + 0] = v0 * s2;
        g_topi[t * 2 + 1] = i1;  g_topw[t * 2 + 1] = v1 * s2;
        atomicAdd(&g_count[i0], 1);
        atomicAdd(&g_count[i1], 1);
#pragma unroll
        for (int e = 0; e < NE; e++) probs_sh[warp][e] = p[e];
    }
    __syncthreads();
    if (threadIdx.x < NE) {
        float s = 0.f;
#pragma unroll
        for (int w = 0; w < 8; w++) s += probs_sh[w][threadIdx.x];
        g_blockprob[blockIdx.x * NE + threadIdx.x] = s;
    }
}

__global__ void offsets_kernel() {
    if (threadIdx.x == 0) {
        int o = 0;
        for (int e = 0; e < NE; e++) { g_off[e] = o; o += g_count[e]; }
    }
}

__global__ void build_kernel() {
    int a = blockIdx.x * blockDim.x + threadIdx.x;
    if (a >= NASSIGN) return;
    int e = g_topi[a];
    int pos = atomicAdd(&g_fill[e], 1);
    int slot = g_off[e] + pos;
    g_rowlist[slot] = a >> 1;
    g_wlist[slot] = g_topw[a];
    g_slot_of[a] = slot;
}

// ==================== fp16 tensor-core grouped GEMMs =======================
// 128x128x32 block tile, 256 threads = 8 warps, warp tile 32x64 via
// mma.sync.m16n8k16.f16 (fp32 accum). Proven 2-stage ping-pong pipeline.

#define BK 32
#define ROW_H 40                 // halves per smem row (32 data + 8 pad)
#define TILE_H (128 * ROW_H)     // halves per operand tile
#define STAGE_H (2 * TILE_H)     // A tile + B tile, halves

template<int KDIM, int NDIM, bool IS_G1>
__global__ __launch_bounds__(256, 2) void gemm_fp16()
{
    __shared__ __align__(16) __half smem[2 * STAGE_H];   // 40960 B

    int e = blockIdx.z;
    int M = g_count[e];
    int m0 = blockIdx.y * 128;
    if (m0 >= M) return;
    int n0 = blockIdx.x * 128;
    int base = g_off[e];
    const __half* Wt = (IS_G1 ? g_w1h : g_w2h) + (size_t)e * KDIM * NDIM;  // [N][K]

    int tid = threadIdx.x;
    int lane = tid & 31, warp = tid >> 5;
    int wm = (warp & 3) * 32;
    int wn = (warp >> 2) * 64;
    int g = lane >> 2, tig = lane & 3;

    // cp.async mapping: 4 threads per row, rows (tid>>2) and 64+(tid>>2)
    int lrow = tid >> 2, chunk = tid & 3;     // chunk*8 halves = chunk*16 bytes
    const __half* aptr[2];
    const __half* bptr[2];
#pragma unroll
    for (int it = 0; it < 2; it++) {
        int r = m0 + lrow + it * 64; if (r >= M) r = M - 1;
        aptr[it] = IS_G1 ? (g_xh + (size_t)g_rowlist[base + r] * KDIM)
                         : (g_h + (size_t)(base + r) * KDIM);
        bptr[it] = Wt + (size_t)(n0 + lrow + it * 64) * KDIM;
    }

    float acc[2][8][4];
#pragma unroll
    for (int i = 0; i < 2; i++)
#pragma unroll
        for (int j = 0; j < 8; j++)
#pragma unroll
            for (int c = 0; c < 4; c++) acc[i][j][c] = 0.f;

    const int NT = KDIM / BK;

#define LOAD_STAGE(ti, s) do {                                                  \
        __half* ab = smem + (s) * STAGE_H;                                      \
        __half* bb = ab + TILE_H;                                               \
        _Pragma("unroll")                                                       \
        for (int it = 0; it < 2; it++) {                                        \
            int rr = lrow + it * 64;                                            \
            cp16(ab + rr * ROW_H + chunk * 8, aptr[it] + (ti) * BK + chunk * 8);\
            cp16(bb + rr * ROW_H + chunk * 8, bptr[it] + (ti) * BK + chunk * 8);\
        }                                                                       \
        CP_COMMIT();                                                            \
    } while (0)

    LOAD_STAGE(0, 0);

    for (int kt = 0; kt < NT; kt++) {
        int cur = kt & 1;
        if (kt + 1 < NT) {
            LOAD_STAGE(kt + 1, cur ^ 1);
            CP_WAIT(1);
        } else {
            CP_WAIT(0);
        }
        __syncthreads();

        const __half* Ac = smem + cur * STAGE_H;
        const __half* Bc = Ac + TILE_H;
#pragma unroll
        for (int ks = 0; ks < 2; ks++) {
            uint32_t af[2][4];
#pragma unroll
            for (int i = 0; i < 2; i++) {
                const __half* ar = Ac + (wm + i * 16 + g) * ROW_H + ks * 16 + 2 * tig;
                af[i][0] = *(const uint32_t*)(ar);
                af[i][1] = *(const uint32_t*)(ar + 8 * ROW_H);
                af[i][2] = *(const uint32_t*)(ar + 8);
                af[i][3] = *(const uint32_t*)(ar + 8 * ROW_H + 8);
            }
            uint32_t bf[8][2];
#pragma unroll
            for (int j = 0; j < 8; j++) {
                const __half* br = Bc + (wn + j * 8 + g) * ROW_H + ks * 16 + 2 * tig;
                bf[j][0] = *(const uint32_t*)(br);
                bf[j][1] = *(const uint32_t*)(br + 8);
            }
#pragma unroll
            for (int i = 0; i < 2; i++)
#pragma unroll
                for (int j = 0; j < 8; j++) mma_fp16(acc[i][j], af[i], bf[j]);
        }
        __syncthreads();
    }

    // epilogue
#pragma unroll
    for (int i = 0; i < 2; i++) {
        int r0 = m0 + wm + i * 16 + g;
        int r1 = r0 + 8;
        if (IS_G1) {
#pragma unroll
            for (int j = 0; j < 8; j++) {
                int col = n0 + wn + j * 8 + 2 * tig;
                if (r0 < M) {
                    float v0 = acc[i][j][0], v1 = acc[i][j][1];
                    __half2 o = __floats2half2_rn(
                        0.5f * v0 * (1.0f + erff(v0 * 0.70710678118654752f)),
                        0.5f * v1 * (1.0f + erff(v1 * 0.70710678118654752f)));
                    *(__half2*)(g_h + (size_t)(base + r0) * NDIM + col) = o;
                }
                if (r1 < M) {
                    float v2 = acc[i][j][2], v3 = acc[i][j][3];
                    __half2 o = __floats2half2_rn(
                        0.5f * v2 * (1.0f + erff(v2 * 0.70710678118654752f)),
                        0.5f * v3 * (1.0f + erff(v3 * 0.70710678118654752f)));
                    *(__half2*)(g_h + (size_t)(base + r1) * NDIM + col) = o;
                }
            }
        } else {
            float w0 = (r0 < M) ? g_wlist[base + r0] : 0.f;
            float w1 = (r1 < M) ? g_wlist[base + r1] : 0.f;
#pragma unroll
            for (int j = 0; j < 8; j++) {
                int col = n0 + wn + j * 8 + 2 * tig;
                if (r0 < M) {
                    float2 o = make_float2(w0 * acc[i][j][0], w0 * acc[i][j][1]);
                    *(float2*)(g_y + (size_t)(base + r0) * NDIM + col) = o;
                }
                if (r1 < M) {
                    float2 o = make_float2(w1 * acc[i][j][2], w1 * acc[i][j][3]);
                    *(float2*)(g_y + (size_t)(base + r1) * NDIM + col) = o;
                }
            }
        }
    }
}

// ----------------- combine: out[t] = y[slot0] + y[slot1] -------------------
__global__ void combine_kernel(float* __restrict__ out) {
    int idx = blockIdx.x * blockDim.x + threadIdx.x;
    if (idx >= TOKS * DM / 4) return;
    int t  = idx / (DM / 4);
    int d4 = idx % (DM / 4);
    int s0 = g_slot_of[t * 2 + 0];
    int s1 = g_slot_of[t * 2 + 1];
    float4 a = *(const float4*)(g_y + (size_t)s0 * DM + d4 * 4);
    float4 b = *(const float4*)(g_y + (size_t)s1 * DM + d4 * 4);
    ((float4*)out)[idx] = make_float4(a.x + b.x, a.y + b.y, a.z + b.z, a.w + b.w);
}

// ----------------- load-balance loss ---------------------------------------
__global__ void loss_kernel(float* __restrict__ out, int out_size) {
    __shared__ float sh[256];
    int e = threadIdx.x & 7, part = threadIdx.x >> 3;
    float s = 0.f;
    for (int b = part; b < GATE_BLOCKS; b += 32) s += g_blockprob[b * NE + e];
    sh[threadIdx.x] = s;
    __syncthreads();
    if (threadIdx.x < NE) {
        float rp = 0.f;
        for (int p = 0; p < 32; p++) rp += sh[p * NE + threadIdx.x];
        rp /= (float)TOKS;
        float usage = (float)g_count[threadIdx.x] / (float)NASSIGN;
        sh[threadIdx.x] = rp * usage;
    }
    __syncthreads();
    if (threadIdx.x == 0) {
        float loss = 0.f;
        for (int e2 = 0; e2 < NE; e2++) loss += sh[e2];
        loss *= (float)NE;
        if (out_size > TOKS * DM) out[TOKS * DM] = loss;
    }
}

// ---------------------------------------------------------------------------
extern "C" void kernel_launch(void* const* d_in, const int* in_sizes, int n_in,
                              void* d_out, int out_size)
{
    const float* x  = (const float*)d_in[0];
    const float* Wg = (const float*)d_in[1];
    const float* W1 = (const float*)d_in[2];
    const float* W2 = (const float*)d_in[3];
    float* out = (float*)d_out;

    zero_counters<<<1, 32>>>();
    convert_x<<<(TOKS * DM / 4 + 255) / 256, 256>>>(x);
    transpose_convert<true><<<dim3(DFF / 32, DM / 32, NE), 256>>>(W1);
    transpose_convert<false><<<dim3(DM / 32, DFF / 32, NE), 256>>>(W2);
    gate_kernel<<<GATE_BLOCKS, 256>>>(x, Wg);
    offsets_kernel<<<1, 32>>>();
    build_kernel<<<(NASSIGN + 255) / 256, 256>>>();

    gemm_fp16<DM, DFF, true><<<dim3(DFF / 128, NASSIGN / 128, NE), 256>>>();
    gemm_fp16<DFF, DM, false><<<dim3(DM / 128, NASSIGN / 128, NE), 256>>>();

    combine_kernel<<<(TOKS * DM / 4 + 255) / 256, 256>>>(out);
    loss_kernel<<<1, 256>>>(out, out_size);
}